// round 16
// baseline (speedup 1.0000x reference)
#include <cuda_runtime.h>
#include <cuda_fp16.h>
#include <math.h>
#include <stdint.h>

// Problem constants
#define B_ 32
#define S_ 128
#define H_ 512
#define K_ 8

// Scratch (device globals — no runtime allocation allowed)
__device__ __half g_xh[2ull * 32 * 128 * 512];   // inputs fp16-hi (0=aspect,1=polarity)
__device__ __half g_xl[2ull * 32 * 128 * 512];   // inputs fp16-lo
__device__ __half g_gth[2ull * 4096 * 512];      // G^T fp16-hi per branch
__device__ __half g_gtl[2ull * 4096 * 512];      // G^T fp16-lo
__device__ __half g_phi[2ull * 4096 * 4096];     // proj fp16-hi
__device__ __half g_plo[2ull * 4096 * 4096];     // proj fp16-lo
__device__ __half g_ath[64ull * 128 * 128];      // attn fp16-hi  [z][s][t]
__device__ __half g_atl[64ull * 128 * 128];      // attn fp16-lo
__device__ __half g_vth[2ull * 32 * 512 * 128];  // values^T fp16-hi [which][b][h][t]
__device__ __half g_vtl[2ull * 32 * 512 * 128];  // values^T fp16-lo

// ===========================================================================
// PTX helpers
// ===========================================================================
__device__ __forceinline__ uint32_t smem_to_u32(const void* p) {
    uint32_t a;
    asm("{ .reg .u64 t; cvta.to.shared.u64 t, %1; cvt.u32.u64 %0, t; }"
        : "=r"(a) : "l"(p));
    return a;
}
__device__ __forceinline__ void cp16(uint32_t s, const void* g) {
    asm volatile(
        "{ .reg .u64 gg; cvta.to.global.u64 gg, %1;"
        "  cp.async.cg.shared.global [%0], [gg], 16; }"
        :: "r"(s), "l"(g));
}
__device__ __forceinline__ void cp_commit() {
    asm volatile("cp.async.commit_group;" ::: "memory");
}
__device__ __forceinline__ void cp_wait1() {
    asm volatile("cp.async.wait_group 1;" ::: "memory");
}
__device__ __forceinline__ void cp_wait2() {
    asm volatile("cp.async.wait_group 2;" ::: "memory");
}
__device__ __forceinline__ void ldsm4(uint32_t& r0, uint32_t& r1, uint32_t& r2,
                                      uint32_t& r3, uint32_t addr) {
    asm volatile("ldmatrix.sync.aligned.m8n8.x4.shared.b16 {%0,%1,%2,%3}, [%4];"
                 : "=r"(r0), "=r"(r1), "=r"(r2), "=r"(r3) : "r"(addr));
}
__device__ __forceinline__ void mma16816(float (&d)[4], const uint32_t (&a)[4],
                                         const uint32_t (&b)[2]) {
    asm volatile(
        "mma.sync.aligned.m16n8k16.row.col.f32.f16.f16.f32 "
        "{%0,%1,%2,%3}, {%4,%5,%6,%7}, {%8,%9}, {%0,%1,%2,%3};"
        : "+f"(d[0]), "+f"(d[1]), "+f"(d[2]), "+f"(d[3])
        : "r"(a[0]), "r"(a[1]), "r"(a[2]), "r"(a[3]), "r"(b[0]), "r"(b[1]));
}
__device__ __forceinline__ void split_h(float x, __half& h, __half& l) {
    h = __float2half_rn(x);
    l = __float2half_rn(x - __half2float(h));
}

// ===========================================================================
// Prep kernels
// ===========================================================================
__global__ __launch_bounds__(256) void k_prep_xv(const float* __restrict__ a,
                                                 const float* __restrict__ p) {
    __shared__ float t[32][33];
    const int z = blockIdx.z;
    const int which = z >> 5, b = z & 31;
    const float* src = (which ? p : a) + (size_t)b * 128 * 512;
    const int h0 = blockIdx.x * 32, t0 = blockIdx.y * 32;
#pragma unroll
    for (int j = 0; j < 4; j++)
        t[threadIdx.y + j * 8][threadIdx.x] =
            src[(size_t)(t0 + threadIdx.y + j * 8) * 512 + h0 + threadIdx.x];
    __syncthreads();

    __half* XH = g_xh + (size_t)which * (32 * 128 * 512) + (size_t)b * 128 * 512;
    __half* XL = g_xl + (size_t)which * (32 * 128 * 512) + (size_t)b * 128 * 512;
#pragma unroll
    for (int j = 0; j < 4; j++) {
        const int tt = t0 + threadIdx.y + j * 8;
        const int hh = h0 + threadIdx.x;
        __half h, l;
        split_h(t[threadIdx.y + j * 8][threadIdx.x], h, l);
        XH[(size_t)tt * 512 + hh] = h;
        XL[(size_t)tt * 512 + hh] = l;
    }

    __half* VH = g_vth + (size_t)z * 512 * 128;
    __half* VL = g_vtl + (size_t)z * 512 * 128;
#pragma unroll
    for (int j = 0; j < 4; j++) {
        const int h = h0 + threadIdx.y + j * 8;
        const int tt = t0 + threadIdx.x;
        __half hh, ll;
        split_h(t[threadIdx.x][threadIdx.y + j * 8], hh, ll);
        VH[(size_t)h * 128 + tt] = hh;
        VL[(size_t)h * 128 + tt] = ll;
    }
}

// Transpose G[br][512 h, 4096 n] -> GT[br][4096 n, 512 h] as fp16 hi/lo
__global__ __launch_bounds__(256) void k_prep_g(const float* __restrict__ Gap,
                                                const float* __restrict__ Gpa) {
    __shared__ float t[32][33];
    const int br = blockIdx.z;
    const float* G = br ? Gpa : Gap;
    const int n0 = blockIdx.x * 32, k0 = blockIdx.y * 32;
#pragma unroll
    for (int j = 0; j < 4; j++)
        t[threadIdx.y + j * 8][threadIdx.x] =
            G[(size_t)(k0 + threadIdx.y + j * 8) * 4096 + n0 + threadIdx.x];
    __syncthreads();
    __half* GH = g_gth + (size_t)br * 4096 * 512;
    __half* GL = g_gtl + (size_t)br * 4096 * 512;
#pragma unroll
    for (int j = 0; j < 4; j++) {
        const int n = n0 + threadIdx.y + j * 8;
        const int k = k0 + threadIdx.x;
        __half h, l;
        split_h(t[threadIdx.x][threadIdx.y + j * 8], h, l);
        GH[(size_t)n * 512 + k] = h;
        GL[(size_t)n * 512 + k] = l;
    }
}

// ===========================================================================
// Tiling constants
// ===========================================================================
// Padded K16 path (gemm2/gemm3): rows 24 halves
#define ROWH 24
#define MATB (128 * ROWH * 2)  // 6144 B per matrix tile
#define BUFB (4 * MATB)        // 24576 B per stage
#define GSMEM (3 * BUFB)       // 73728 B (gemm3, 3-stage)
#define GSMEM2 (4 * BUFB)      // 98304 B (gemm2, 4-stage)

// Swizzled K32 path (gemm1): rows = exactly 64 B (32 halves), no pad.
// phys = row*64 + ((chunk16 + row) & 3) * 16. k-step 0->1: chunk += 2 -> ^32.
#define MAT32B 8192            // 128 * 64 B
#define BUF32B (4 * MAT32B)    // 32768 B per stage
#define GSMEM1 (3 * BUF32B)    // 98304 B, 3-stage, 2 CTAs/SM

// Batched fragment-load + MMA body for a 64x64 warp tile (3x split),
// padded-layout offsets (gemm2/gemm3 path).
#define WARP_TILE_BODY64(mb, offA, offB, acc)                                \
    {                                                                        \
        uint32_t ah[4][4], al[4][4];                                         \
        _Pragma("unroll") for (int fm = 0; fm < 4; fm++) {                   \
            ldsm4(ah[fm][0], ah[fm][1], ah[fm][2], ah[fm][3],                \
                  (mb) + 0 * MATB + (offA)[fm]);                             \
            ldsm4(al[fm][0], al[fm][1], al[fm][2], al[fm][3],                \
                  (mb) + 1 * MATB + (offA)[fm]);                             \
        }                                                                    \
        uint32_t bh[8][2], bl[8][2];                                         \
        _Pragma("unroll") for (int p = 0; p < 4; p++) {                      \
            ldsm4(bh[2 * p][0], bh[2 * p][1], bh[2 * p + 1][0],              \
                  bh[2 * p + 1][1], (mb) + 2 * MATB + (offB)[p]);            \
            ldsm4(bl[2 * p][0], bl[2 * p][1], bl[2 * p + 1][0],              \
                  bl[2 * p + 1][1], (mb) + 3 * MATB + (offB)[p]);            \
        }                                                                    \
        _Pragma("unroll") for (int fm = 0; fm < 4; fm++)                     \
            _Pragma("unroll") for (int fn = 0; fn < 8; fn++) {               \
                mma16816((acc)[fm][fn], ah[fm], bh[fn]);                     \
                mma16816((acc)[fm][fn], ah[fm], bl[fn]);                     \
                mma16816((acc)[fm][fn], al[fm], bh[fn]);                     \
            }                                                                \
    }

// ===========================================================================
// GEMM1 (fp16 3x split, NT): proj[br] = aspect[4096,512] @ GT[br]^T
// 128 threads (4 warps), CTA 128x128, warp tile 64x64, K chunk 32
// (2 k-steps per barrier), 3-stage swizzled smem, wait_group 1, 2 CTAs/SM.
// ===========================================================================
__global__ __launch_bounds__(128, 2) void k_gemm1() {
    extern __shared__ __half sh[];
    const uint32_t sb = smem_to_u32(sh);
    const int tid = threadIdx.x;
    const int wid = tid >> 5, lane = tid & 31;
    const int g = lane >> 2, tig = lane & 3;
    const int sub = lane >> 3, r = lane & 7;
    const int wm = (wid & 1) * 64, wn = (wid >> 1) * 64;

    const int br = blockIdx.z;
    const int m0 = blockIdx.y * 128;
    const int n0 = blockIdx.x * 128;

    const __half* Ah = g_xh + (size_t)m0 * 512;
    const __half* Al = g_xl + (size_t)m0 * 512;
    const __half* Bh = g_gth + ((size_t)br * 4096 + n0) * 512;
    const __half* Bl = g_gtl + ((size_t)br * 4096 + n0) * 512;

    // LDSM swizzled offsets (ks = 0; ks = 1 is off ^ 32)
    uint32_t offA[4], offB[4];
#pragma unroll
    for (int fm = 0; fm < 4; fm++) {
        const int row = wm + fm * 16 + (sub & 1) * 8 + r;
        const int c = sub >> 1;
        offA[fm] = (uint32_t)(row * 64 + (((c + row) & 3) * 16));
    }
#pragma unroll
    for (int p = 0; p < 4; p++) {
        const int row = wn + p * 16 + (sub >> 1) * 8 + r;
        const int c = sub & 1;
        offB[p] = (uint32_t)(row * 64 + (((c + row) & 3) * 16));
    }

    // Loader: thread covers rows {lr, lr+64}, chunks {j0, j0+1} (32 B contig).
    const int lr = tid >> 1;
    const int j0 = (tid & 1) * 2;

    float acc[4][8][4] = {};

#define G1_SW(row, ch) ((uint32_t)((row) * 64 + ((((ch) + (row)) & 3) * 16)))
#define G1_LOAD(kc, buf)                                                     \
    {                                                                        \
        const uint32_t bb_ = sb + (buf) * BUF32B;                            \
        _Pragma("unroll") for (int rr = 0; rr < 2; rr++) {                   \
            const int row_ = lr + rr * 64;                                   \
            const size_t gs_ = (size_t)row_ * 512 + (kc) * 32 + j0 * 8;      \
            _Pragma("unroll") for (int jj = 0; jj < 2; jj++) {               \
                const uint32_t sw_ = G1_SW(row_, j0 + jj);                   \
                cp16(bb_ + 0 * MAT32B + sw_, Ah + gs_ + jj * 8);             \
                cp16(bb_ + 1 * MAT32B + sw_, Al + gs_ + jj * 8);             \
                cp16(bb_ + 2 * MAT32B + sw_, Bh + gs_ + jj * 8);             \
                cp16(bb_ + 3 * MAT32B + sw_, Bl + gs_ + jj * 8);             \
            }                                                                \
        }                                                                    \
    }

    G1_LOAD(0, 0);
    cp_commit();
    G1_LOAD(1, 1);
    cp_commit();

#pragma unroll 1
    for (int c = 0; c < 16; c++) {
        cp_wait1();
        __syncthreads();
        const uint32_t mb = sb + (c % 3) * BUF32B;
        if (c + 2 < 16) G1_LOAD(c + 2, (c + 2) % 3);
        cp_commit();

#pragma unroll
        for (int ks = 0; ks < 2; ks++) {
            const uint32_t kx = ks << 5;  // chunk +2 == XOR 32 in swizzle
            uint32_t ah[4][4], al[4][4];
#pragma unroll
            for (int fm = 0; fm < 4; fm++) {
                ldsm4(ah[fm][0], ah[fm][1], ah[fm][2], ah[fm][3],
                      mb + 0 * MAT32B + (offA[fm] ^ kx));
                ldsm4(al[fm][0], al[fm][1], al[fm][2], al[fm][3],
                      mb + 1 * MAT32B + (offA[fm] ^ kx));
            }
            uint32_t bh[8][2], bl[8][2];
#pragma unroll
            for (int p = 0; p < 4; p++) {
                ldsm4(bh[2 * p][0], bh[2 * p][1], bh[2 * p + 1][0],
                      bh[2 * p + 1][1], mb + 2 * MAT32B + (offB[p] ^ kx));
                ldsm4(bl[2 * p][0], bl[2 * p][1], bl[2 * p + 1][0],
                      bl[2 * p + 1][1], mb + 3 * MAT32B + (offB[p] ^ kx));
            }
#pragma unroll
            for (int fm = 0; fm < 4; fm++)
#pragma unroll
                for (int fn = 0; fn < 8; fn++) {
                    mma16816(acc[fm][fn], ah[fm], bh[fn]);
                    mma16816(acc[fm][fn], ah[fm], bl[fn]);
                    mma16816(acc[fm][fn], al[fm], bh[fn]);
                }
        }
    }

    const size_t cb = (size_t)br * 4096 * 4096;
#pragma unroll
    for (int fm = 0; fm < 4; fm++)
#pragma unroll
        for (int fn = 0; fn < 8; fn++) {
            const int row = m0 + wm + fm * 16 + g;
            const int col = n0 + wn + fn * 8 + tig * 2;
            size_t o = cb + (size_t)row * 4096 + col;
            __half h0, l0, h1, l1;
            split_h(acc[fm][fn][0], h0, l0);
            split_h(acc[fm][fn][1], h1, l1);
            *(__half2*)&g_phi[o] = __halves2half2(h0, h1);
            *(__half2*)&g_plo[o] = __halves2half2(l0, l1);
            o += (size_t)8 * 4096;
            split_h(acc[fm][fn][2], h0, l0);
            split_h(acc[fm][fn][3], h1, l1);
            *(__half2*)&g_phi[o] = __halves2half2(h0, h1);
            *(__half2*)&g_plo[o] = __halves2half2(l0, l1);
        }
}

// ===========================================================================
// GEMM2 fused (128 thr, 4 warps 64x64, K chunk 16, 4-stage, batched LDSM):
// C2 = proj_b @ right_b^T; epilogue tanh + v-dot (k = g per lane) +
// block softmax -> attn fp16 hi/lo.  [R15 proven]
// ===========================================================================
__global__ __launch_bounds__(128, 2) void k_gemm2(const float* __restrict__ va,
                                                  const float* __restrict__ vp) {
    extern __shared__ __half sh[];
    const uint32_t sb = smem_to_u32(sh);
    float* sc = (float*)sh;  // reused after mainloop: [16][132]
    const int tid = threadIdx.x;
    const int wid = tid >> 5, lane = tid & 31;
    const int g = lane >> 2, tig = lane & 3;
    const int sub = lane >> 3, r = lane & 7;
    const int wm = (wid & 1) * 64, wn = (wid >> 1) * 64;

    const int z = blockIdx.y;
    const int br = z >> 5, b = z & 31;
    const int sB = blockIdx.x * 16;

    const size_t pb = (size_t)br * 4096 * 4096;
    const int rsel = br ? 0 : 1;
    const __half* Rh = g_xh + (size_t)rsel * (32 * 128 * 512) + (size_t)b * 128 * 512;
    const __half* Rl = g_xl + (size_t)rsel * (32 * 128 * 512) + (size_t)b * 128 * 512;

    uint32_t offA[4], offB[4];
#pragma unroll
    for (int fm = 0; fm < 4; fm++)
        offA[fm] = ((wm + fm * 16 + (sub & 1) * 8 + r) * ROWH + (sub >> 1) * 8) * 2;
#pragma unroll
    for (int p = 0; p < 4; p++)
        offB[p] = ((wn + p * 16 + (sub >> 1) * 8 + r) * ROWH + (sub & 1) * 8) * 2;

    const int lrow = tid >> 1, lcol = (tid & 1) * 8;
    const uint32_t sd0 = (uint32_t)(lrow * ROWH + lcol) * 2;
    const uint32_t sd1 = sd0 + 64 * ROWH * 2;
    const size_t aoff = ((size_t)(b * 128 + sB + (lrow >> 3))) * 4096 +
                        (size_t)(lrow & 7) * 512 + lcol;
    const __half* PAh = g_phi + pb + aoff;
    const __half* PAl = g_plo + pb + aoff;
    const __half* PBh = Rh + (size_t)lrow * 512 + lcol;
    const __half* PBl = Rl + (size_t)lrow * 512 + lcol;

    float acc[4][8][4] = {};

#define G2_LOAD(kc, buf)                                                 \
    {                                                                    \
        const uint32_t bb_ = sb + (buf) * BUFB;                          \
        const int ko_ = (kc) * 16;                                       \
        cp16(bb_ + 0 * MATB + sd0, PAh + ko_);                           \
        cp16(bb_ + 0 * MATB + sd1, PAh + ko_ + (size_t)8 * 4096);        \
        cp16(bb_ + 1 * MATB + sd0, PAl + ko_);                           \
        cp16(bb_ + 1 * MATB + sd1, PAl + ko_ + (size_t)8 * 4096);        \
        cp16(bb_ + 2 * MATB + sd0, PBh + ko_);                           \
        cp16(bb_ + 2 * MATB + sd1, PBh + ko_ + (size_t)64 * 512);        \
        cp16(bb_ + 3 * MATB + sd0, PBl + ko_);                           \
        cp16(bb_ + 3 * MATB + sd1, PBl + ko_ + (size_t)64 * 512);        \
    }

    G2_LOAD(0, 0);
    cp_commit();
    G2_LOAD(1, 1);
    cp_commit();
    G2_LOAD(2, 2);
    cp_commit();

#pragma unroll 1
    for (int c = 0; c < 32; c++) {
        cp_wait2();
        __syncthreads();
        const uint32_t mb = sb + (c & 3) * BUFB;
        if (c + 3 < 32) G2_LOAD(c + 3, (c + 3) & 3);
        cp_commit();
        WARP_TILE_BODY64(mb, offA, offB, acc);
    }

    // Epilogue part 1: tanh, weight by v[g] (k = g per lane), shfl-reduce k.
    const float* vv = br ? vp : va;
    const float vg = vv[g];
#pragma unroll
    for (int fm = 0; fm < 4; fm++)
#pragma unroll
        for (int fn = 0; fn < 8; fn++)
#pragma unroll
            for (int j = 0; j < 4; j++)
                acc[fm][fn][j] = vg * tanhf(acc[fm][fn][j]);
#pragma unroll
    for (int off = 16; off >= 4; off >>= 1)
#pragma unroll
        for (int fm = 0; fm < 4; fm++)
#pragma unroll
            for (int fn = 0; fn < 8; fn++)
#pragma unroll
                for (int j = 0; j < 4; j++)
                    acc[fm][fn][j] +=
                        __shfl_xor_sync(0xffffffffu, acc[fm][fn][j], off);

    __syncthreads();  // mainloop smem dead; reuse as score tile [16][132]
    if (lane < 4) {   // g == 0 lanes hold the k-sums
#pragma unroll
        for (int fm = 0; fm < 4; fm++)
#pragma unroll
            for (int si = 0; si < 2; si++) {
                const int srow = (wm >> 3) + 2 * fm + si;
#pragma unroll
                for (int fn = 0; fn < 8; fn++) {
                    sc[srow * 132 + wn + fn * 8 + tig * 2] = acc[fm][fn][si * 2];
                    sc[srow * 132 + wn + fn * 8 + tig * 2 + 1] =
                        acc[fm][fn][si * 2 + 1];
                }
            }
    }
    __syncthreads();

    // Epilogue part 2: softmax over t=128 per s row (8 threads/row).
    {
        const int row = tid >> 3, l8 = tid & 7;
        float vals[16];
        float mx = -1e30f;
#pragma unroll
        for (int i = 0; i < 16; i++) {
            vals[i] = sc[row * 132 + l8 * 16 + i];
            mx = fmaxf(mx, vals[i]);
        }
#pragma unroll
        for (int off = 1; off <= 4; off <<= 1)
            mx = fmaxf(mx, __shfl_xor_sync(0xffffffffu, mx, off));
        float sm = 0.f;
#pragma unroll
        for (int i = 0; i < 16; i++) {
            vals[i] = expf(vals[i] - mx);
            sm += vals[i];
        }
#pragma unroll
        for (int off = 1; off <= 4; off <<= 1)
            sm += __shfl_xor_sync(0xffffffffu, sm, off);
        const float inv = 1.f / sm;
        const size_t base = (size_t)z * 16384 + (size_t)(sB + row) * 128 + l8 * 16;
#pragma unroll
        for (int i = 0; i < 16; i += 2) {
            __half h0, l0, h1, l1;
            split_h(vals[i] * inv, h0, l0);
            split_h(vals[i + 1] * inv, h1, l1);
            *(__half2*)&g_ath[base + i] = __halves2half2(h0, h1);
            *(__half2*)&g_atl[base + i] = __halves2half2(l0, l1);
        }
    }
}

// ===========================================================================
// GEMM3 (fp16 3x split, NT): out = bias + attn[128,128] @ V^T[512,128]^T
// grid (4 h-blocks, 64 z), 256 threads, CTA 128x128, K = t = 128 (8 chunks).
// [R14/R15 proven]
// ===========================================================================
__global__ __launch_bounds__(256) void k_gemm3(const float* __restrict__ aspect,
                                               const float* __restrict__ polarity,
                                               float* __restrict__ out) {
    extern __shared__ __half sh[];
    const uint32_t sb = smem_to_u32(sh);
    const int tid = threadIdx.x;
    const int wid = tid >> 5, lane = tid & 31;
    const int g = lane >> 2, tig = lane & 3;
    const int sub = lane >> 3, r = lane & 7;
    const int wm = (wid & 3) * 32, wn = (wid >> 2) * 64;

    const int z = blockIdx.y;
    const int br = z >> 5, b = z & 31;
    const int h0 = blockIdx.x * 128;

    const int vsel = br ? 0 : 1;
    const __half* Ah = g_ath + (size_t)z * 16384;
    const __half* Al = g_atl + (size_t)z * 16384;
    const __half* Bh = g_vth + ((size_t)(vsel * 32 + b) * 512 + h0) * 128;
    const __half* Bl = g_vtl + ((size_t)(vsel * 32 + b) * 512 + h0) * 128;

    uint32_t offA[2];
#pragma unroll
    for (int fm = 0; fm < 2; fm++)
        offA[fm] = ((wm + fm * 16 + (sub & 1) * 8 + r) * ROWH + (sub >> 1) * 8) * 2;
    uint32_t offB[4];
#pragma unroll
    for (int p = 0; p < 4; p++)
        offB[p] = ((wn + p * 16 + (sub >> 1) * 8 + r) * ROWH + (sub & 1) * 8) * 2;

    const int lrow = tid >> 1, lh = (tid & 1) * 8;
    const uint32_t sdst = (uint32_t)(lrow * ROWH + lh) * 2;

    float acc[2][8][4] = {};

#define G3_LOAD(kc, buf)                                                    \
    {                                                                       \
        const uint32_t bb_ = sb + (buf) * BUFB;                             \
        const size_t so_ = (size_t)lrow * 128 + (kc) * 16 + lh;             \
        cp16(bb_ + 0 * MATB + sdst, Ah + so_);                              \
        cp16(bb_ + 1 * MATB + sdst, Al + so_);                              \
        cp16(bb_ + 2 * MATB + sdst, Bh + so_);                              \
        cp16(bb_ + 3 * MATB + sdst, Bl + so_);                              \
    }

    G3_LOAD(0, 0);
    cp_commit();
    G3_LOAD(1, 1);
    cp_commit();

#pragma unroll 1
    for (int c = 0; c < 8; c++) {
        cp_wait1();
        __syncthreads();
        const int buf = c % 3;
        if (c + 2 < 8) G3_LOAD(c + 2, (c + 2) % 3);
        cp_commit();
        const uint32_t mb = sb + buf * BUFB;

        uint32_t ah[2][4], al[2][4];
#pragma unroll
        for (int fm = 0; fm < 2; fm++) {
            ldsm4(ah[fm][0], ah[fm][1], ah[fm][2], ah[fm][3], mb + 0 * MATB + offA[fm]);
            ldsm4(al[fm][0], al[fm][1], al[fm][2], al[fm][3], mb + 1 * MATB + offA[fm]);
        }
        uint32_t bh[8][2], bl[8][2];
#pragma unroll
        for (int p = 0; p < 4; p++) {
            ldsm4(bh[2 * p][0], bh[2 * p][1], bh[2 * p + 1][0], bh[2 * p + 1][1],
                  mb + 2 * MATB + offB[p]);
            ldsm4(bl[2 * p][0], bl[2 * p][1], bl[2 * p + 1][0], bl[2 * p + 1][1],
                  mb + 3 * MATB + offB[p]);
        }
#pragma unroll
        for (int fm = 0; fm < 2; fm++)
#pragma unroll
            for (int fn = 0; fn < 8; fn++) {
                mma16816(acc[fm][fn], ah[fm], bh[fn]);
                mma16816(acc[fm][fn], ah[fm], bl[fn]);
                mma16816(acc[fm][fn], al[fm], bh[fn]);
            }
    }

    const float* bias = (br ? polarity : aspect) + (size_t)b * 128 * 512;
    float* C = out + (size_t)br * (32 * 128 * 512) + (size_t)b * 128 * 512;
#pragma unroll
    for (int fm = 0; fm < 2; fm++)
#pragma unroll
        for (int fn = 0; fn < 8; fn++) {
            const int row = wm + fm * 16 + g;
            const int col = h0 + wn + fn * 8 + tig * 2;
            size_t o = (size_t)row * 512 + col;
            float2 bv = *(const float2*)&bias[o];
            *(float2*)&C[o] =
                make_float2(bv.x + acc[fm][fn][0], bv.y + acc[fm][fn][1]);
            o += (size_t)8 * 512;
            bv = *(const float2*)&bias[o];
            *(float2*)&C[o] =
                make_float2(bv.x + acc[fm][fn][2], bv.y + acc[fm][fn][3]);
        }
}

// ---------------------------------------------------------------------------
extern "C" void kernel_launch(void* const* d_in, const int* in_sizes, int n_in,
                              void* d_out, int out_size) {
    const float* aspect = (const float*)d_in[0];
    const float* polarity = (const float*)d_in[1];
    const float* Gap = (const float*)d_in[2];
    const float* Gpa = (const float*)d_in[3];
    const float* va = (const float*)d_in[4];
    const float* vp = (const float*)d_in[5];
    float* out = (float*)d_out;

    cudaFuncSetAttribute(k_gemm1, cudaFuncAttributeMaxDynamicSharedMemorySize, GSMEM1);
    cudaFuncSetAttribute(k_gemm2, cudaFuncAttributeMaxDynamicSharedMemorySize, GSMEM2);
    cudaFuncSetAttribute(k_gemm3, cudaFuncAttributeMaxDynamicSharedMemorySize, GSMEM);

    k_prep_xv<<<dim3(16, 4, 64), dim3(32, 8)>>>(aspect, polarity);
    k_prep_g<<<dim3(128, 16, 2), dim3(32, 8)>>>(Gap, Gpa);
    k_gemm1<<<dim3(32, 32, 2), 128, GSMEM1>>>();
    k_gemm2<<<dim3(8, 64), 128, GSMEM2>>>(va, vp);
    k_gemm3<<<dim3(4, 64), 256, GSMEM>>>(aspect, polarity, out);
}

// round 17
// speedup vs baseline: 1.1019x; 1.1019x over previous
#include <cuda_runtime.h>
#include <cuda_fp16.h>
#include <math.h>
#include <stdint.h>

// Problem constants
#define B_ 32
#define S_ 128
#define H_ 512
#define K_ 8

// Scratch (device globals — no runtime allocation allowed)
__device__ __half g_xh[2ull * 32 * 128 * 512];   // inputs fp16-hi (0=aspect,1=polarity)
__device__ __half g_xl[2ull * 32 * 128 * 512];   // inputs fp16-lo
__device__ __half g_gth[2ull * 4096 * 512];      // G^T fp16-hi per branch
__device__ __half g_gtl[2ull * 4096 * 512];      // G^T fp16-lo
__device__ __half g_phi[2ull * 4096 * 4096];     // proj fp16-hi
__device__ __half g_plo[2ull * 4096 * 4096];     // proj fp16-lo
__device__ __half g_ath[64ull * 128 * 128];      // attn fp16-hi  [z][s][t]
__device__ __half g_atl[64ull * 128 * 128];      // attn fp16-lo
__device__ __half g_vth[2ull * 32 * 512 * 128];  // values^T fp16-hi [which][b][h][t]
__device__ __half g_vtl[2ull * 32 * 512 * 128];  // values^T fp16-lo

// ===========================================================================
// PTX helpers
// ===========================================================================
__device__ __forceinline__ uint32_t smem_to_u32(const void* p) {
    uint32_t a;
    asm("{ .reg .u64 t; cvta.to.shared.u64 t, %1; cvt.u32.u64 %0, t; }"
        : "=r"(a) : "l"(p));
    return a;
}
__device__ __forceinline__ void cp16(uint32_t s, const void* g) {
    asm volatile(
        "{ .reg .u64 gg; cvta.to.global.u64 gg, %1;"
        "  cp.async.cg.shared.global [%0], [gg], 16; }"
        :: "r"(s), "l"(g));
}
__device__ __forceinline__ void cp_commit() {
    asm volatile("cp.async.commit_group;" ::: "memory");
}
__device__ __forceinline__ void cp_wait1() {
    asm volatile("cp.async.wait_group 1;" ::: "memory");
}
__device__ __forceinline__ void cp_wait2() {
    asm volatile("cp.async.wait_group 2;" ::: "memory");
}
__device__ __forceinline__ void ldsm4(uint32_t& r0, uint32_t& r1, uint32_t& r2,
                                      uint32_t& r3, uint32_t addr) {
    asm volatile("ldmatrix.sync.aligned.m8n8.x4.shared.b16 {%0,%1,%2,%3}, [%4];"
                 : "=r"(r0), "=r"(r1), "=r"(r2), "=r"(r3) : "r"(addr));
}
__device__ __forceinline__ void mma16816(float (&d)[4], const uint32_t (&a)[4],
                                         const uint32_t (&b)[2]) {
    asm volatile(
        "mma.sync.aligned.m16n8k16.row.col.f32.f16.f16.f32 "
        "{%0,%1,%2,%3}, {%4,%5,%6,%7}, {%8,%9}, {%0,%1,%2,%3};"
        : "+f"(d[0]), "+f"(d[1]), "+f"(d[2]), "+f"(d[3])
        : "r"(a[0]), "r"(a[1]), "r"(a[2]), "r"(a[3]), "r"(b[0]), "r"(b[1]));
}
__device__ __forceinline__ void split_h(float x, __half& h, __half& l) {
    h = __float2half_rn(x);
    l = __float2half_rn(x - __half2float(h));
}

// ===========================================================================
// Prep kernels
// ===========================================================================
// Fused: read inputs once; write BOTH the [t,h] fp16 hi/lo split (g_xh/g_xl)
// and the transposed [h,t] values split (g_vth/g_vtl).
__global__ __launch_bounds__(256) void k_prep_xv(const float* __restrict__ a,
                                                 const float* __restrict__ p) {
    __shared__ float t[32][33];
    const int z = blockIdx.z;
    const int which = z >> 5, b = z & 31;
    const float* src = (which ? p : a) + (size_t)b * 128 * 512;
    const int h0 = blockIdx.x * 32, t0 = blockIdx.y * 32;
#pragma unroll
    for (int j = 0; j < 4; j++)
        t[threadIdx.y + j * 8][threadIdx.x] =
            src[(size_t)(t0 + threadIdx.y + j * 8) * 512 + h0 + threadIdx.x];
    __syncthreads();

    __half* XH = g_xh + (size_t)which * (32 * 128 * 512) + (size_t)b * 128 * 512;
    __half* XL = g_xl + (size_t)which * (32 * 128 * 512) + (size_t)b * 128 * 512;
#pragma unroll
    for (int j = 0; j < 4; j++) {
        const int tt = t0 + threadIdx.y + j * 8;
        const int hh = h0 + threadIdx.x;
        __half h, l;
        split_h(t[threadIdx.y + j * 8][threadIdx.x], h, l);
        XH[(size_t)tt * 512 + hh] = h;
        XL[(size_t)tt * 512 + hh] = l;
    }

    __half* VH = g_vth + (size_t)z * 512 * 128;
    __half* VL = g_vtl + (size_t)z * 512 * 128;
#pragma unroll
    for (int j = 0; j < 4; j++) {
        const int h = h0 + threadIdx.y + j * 8;
        const int tt = t0 + threadIdx.x;
        __half hh, ll;
        split_h(t[threadIdx.x][threadIdx.y + j * 8], hh, ll);
        VH[(size_t)h * 128 + tt] = hh;
        VL[(size_t)h * 128 + tt] = ll;
    }
}

// Transpose G[br][512 h, 4096 n] -> GT[br][4096 n, 512 h] as fp16 hi/lo
__global__ __launch_bounds__(256) void k_prep_g(const float* __restrict__ Gap,
                                                const float* __restrict__ Gpa) {
    __shared__ float t[32][33];
    const int br = blockIdx.z;
    const float* G = br ? Gpa : Gap;
    const int n0 = blockIdx.x * 32, k0 = blockIdx.y * 32;
#pragma unroll
    for (int j = 0; j < 4; j++)
        t[threadIdx.y + j * 8][threadIdx.x] =
            G[(size_t)(k0 + threadIdx.y + j * 8) * 4096 + n0 + threadIdx.x];
    __syncthreads();
    __half* GH = g_gth + (size_t)br * 4096 * 512;
    __half* GL = g_gtl + (size_t)br * 4096 * 512;
#pragma unroll
    for (int j = 0; j < 4; j++) {
        const int n = n0 + threadIdx.y + j * 8;
        const int k = k0 + threadIdx.x;
        __half h, l;
        split_h(t[threadIdx.x][threadIdx.y + j * 8], h, l);
        GH[(size_t)n * 512 + k] = h;
        GL[(size_t)n * 512 + k] = l;
    }
}

// ===========================================================================
// Tiling constants (rows padded to 24 halves -> LDSM conflict-free)
// ===========================================================================
#define ROWH 24
#define MATB (128 * ROWH * 2)  // 6144 bytes per matrix tile
#define BUFB (4 * MATB)        // 24576 bytes per stage
#define GSMEM (3 * BUFB)       // 73728 bytes (gemm3, 3-stage)
#define GSMEM1 (4 * BUFB)      // 98304 bytes (gemm1/gemm2, 4-stage)

// Batched fragment-load + MMA body for a 64x64 warp tile (3x split).
#define WARP_TILE_BODY64(mb, offA, offB, acc)                                \
    {                                                                        \
        uint32_t ah[4][4], al[4][4];                                         \
        _Pragma("unroll") for (int fm = 0; fm < 4; fm++) {                   \
            ldsm4(ah[fm][0], ah[fm][1], ah[fm][2], ah[fm][3],                \
                  (mb) + 0 * MATB + (offA)[fm]);                             \
            ldsm4(al[fm][0], al[fm][1], al[fm][2], al[fm][3],                \
                  (mb) + 1 * MATB + (offA)[fm]);                             \
        }                                                                    \
        uint32_t bh[8][2], bl[8][2];                                         \
        _Pragma("unroll") for (int p = 0; p < 4; p++) {                      \
            ldsm4(bh[2 * p][0], bh[2 * p][1], bh[2 * p + 1][0],              \
                  bh[2 * p + 1][1], (mb) + 2 * MATB + (offB)[p]);            \
            ldsm4(bl[2 * p][0], bl[2 * p][1], bl[2 * p + 1][0],              \
                  bl[2 * p + 1][1], (mb) + 3 * MATB + (offB)[p]);            \
        }                                                                    \
        _Pragma("unroll") for (int fm = 0; fm < 4; fm++)                     \
            _Pragma("unroll") for (int fn = 0; fn < 8; fn++) {               \
                mma16816((acc)[fm][fn], ah[fm], bh[fn]);                     \
                mma16816((acc)[fm][fn], ah[fm], bl[fn]);                     \
                mma16816((acc)[fm][fn], al[fm], bh[fn]);                     \
            }                                                                \
    }

// ===========================================================================
// GEMM1 (fp16 3x split, NT): proj[br] = aspect[4096,512] @ GT[br]^T
// 128 threads (4 warps), CTA 128x128, warp tile 64x64, K chunk 16,
// 4-stage cp.async (wait_group 2), 2 CTAs/SM. [R11/R14/R15 proven]
// ===========================================================================
__global__ __launch_bounds__(128, 2) void k_gemm1() {
    extern __shared__ __half sh[];
    const uint32_t sb = smem_to_u32(sh);
    const int tid = threadIdx.x;
    const int wid = tid >> 5, lane = tid & 31;
    const int g = lane >> 2, tig = lane & 3;
    const int sub = lane >> 3, r = lane & 7;
    const int wm = (wid & 1) * 64, wn = (wid >> 1) * 64;

    const int br = blockIdx.z;
    const int m0 = blockIdx.y * 128;
    const int n0 = blockIdx.x * 128;

    const __half* Ah = g_xh + (size_t)m0 * 512;
    const __half* Al = g_xl + (size_t)m0 * 512;
    const __half* Bh = g_gth + ((size_t)br * 4096 + n0) * 512;
    const __half* Bl = g_gtl + ((size_t)br * 4096 + n0) * 512;

    uint32_t offA[4], offB[4];
#pragma unroll
    for (int fm = 0; fm < 4; fm++)
        offA[fm] = ((wm + fm * 16 + (sub & 1) * 8 + r) * ROWH + (sub >> 1) * 8) * 2;
#pragma unroll
    for (int p = 0; p < 4; p++)
        offB[p] = ((wn + p * 16 + (sub >> 1) * 8 + r) * ROWH + (sub & 1) * 8) * 2;

    const int lrow = tid >> 1, lcol = (tid & 1) * 8;
    const uint32_t sd0 = (uint32_t)(lrow * ROWH + lcol) * 2;
    const uint32_t sd1 = sd0 + 64 * ROWH * 2;

    float acc[4][8][4] = {};

#define G1_LOAD(kc, buf)                                                 \
    {                                                                    \
        const uint32_t bb_ = sb + (buf) * BUFB;                          \
        const size_t so_ = (size_t)lrow * 512 + (kc) * 16 + lcol;        \
        const size_t so1_ = so_ + (size_t)64 * 512;                      \
        cp16(bb_ + 0 * MATB + sd0, Ah + so_);                            \
        cp16(bb_ + 0 * MATB + sd1, Ah + so1_);                           \
        cp16(bb_ + 1 * MATB + sd0, Al + so_);                            \
        cp16(bb_ + 1 * MATB + sd1, Al + so1_);                           \
        cp16(bb_ + 2 * MATB + sd0, Bh + so_);                            \
        cp16(bb_ + 2 * MATB + sd1, Bh + so1_);                           \
        cp16(bb_ + 3 * MATB + sd0, Bl + so_);                            \
        cp16(bb_ + 3 * MATB + sd1, Bl + so1_);                           \
    }

    G1_LOAD(0, 0);
    cp_commit();
    G1_LOAD(1, 1);
    cp_commit();
    G1_LOAD(2, 2);
    cp_commit();

#pragma unroll 1
    for (int c = 0; c < 32; c++) {
        cp_wait2();
        __syncthreads();
        const uint32_t mb = sb + (c & 3) * BUFB;
        if (c + 3 < 32) G1_LOAD(c + 3, (c + 3) & 3);
        cp_commit();
        WARP_TILE_BODY64(mb, offA, offB, acc);
    }

    const size_t cb = (size_t)br * 4096 * 4096;
#pragma unroll
    for (int fm = 0; fm < 4; fm++)
#pragma unroll
        for (int fn = 0; fn < 8; fn++) {
            const int row = m0 + wm + fm * 16 + g;
            const int col = n0 + wn + fn * 8 + tig * 2;
            size_t o = cb + (size_t)row * 4096 + col;
            __half h0, l0, h1, l1;
            split_h(acc[fm][fn][0], h0, l0);
            split_h(acc[fm][fn][1], h1, l1);
            *(__half2*)&g_phi[o] = __halves2half2(h0, h1);
            *(__half2*)&g_plo[o] = __halves2half2(l0, l1);
            o += (size_t)8 * 4096;
            split_h(acc[fm][fn][2], h0, l0);
            split_h(acc[fm][fn][3], h1, l1);
            *(__half2*)&g_phi[o] = __halves2half2(h0, h1);
            *(__half2*)&g_plo[o] = __halves2half2(l0, l1);
        }
}

// ===========================================================================
// GEMM2 fused (128 thr, 4 warps 64x64, K chunk 16, 4-stage, batched LDSM):
// C2 = proj_b @ right_b^T; epilogue tanh + v-dot (k = g per lane) +
// block softmax -> attn fp16 hi/lo.  [R15 proven]
// grid (8 m-blocks, 64 z). CTA m tile = 128 rows = 16 s x 8 k (row = s*8+k).
// ===========================================================================
__global__ __launch_bounds__(128, 2) void k_gemm2(const float* __restrict__ va,
                                                  const float* __restrict__ vp) {
    extern __shared__ __half sh[];
    const uint32_t sb = smem_to_u32(sh);
    float* sc = (float*)sh;  // reused after mainloop: [16][132]
    const int tid = threadIdx.x;
    const int wid = tid >> 5, lane = tid & 31;
    const int g = lane >> 2, tig = lane & 3;
    const int sub = lane >> 3, r = lane & 7;
    const int wm = (wid & 1) * 64, wn = (wid >> 1) * 64;

    const int z = blockIdx.y;
    const int br = z >> 5, b = z & 31;
    const int sB = blockIdx.x * 16;

    const size_t pb = (size_t)br * 4096 * 4096;
    const int rsel = br ? 0 : 1;
    const __half* Rh = g_xh + (size_t)rsel * (32 * 128 * 512) + (size_t)b * 128 * 512;
    const __half* Rl = g_xl + (size_t)rsel * (32 * 128 * 512) + (size_t)b * 128 * 512;

    uint32_t offA[4], offB[4];
#pragma unroll
    for (int fm = 0; fm < 4; fm++)
        offA[fm] = ((wm + fm * 16 + (sub & 1) * 8 + r) * ROWH + (sub >> 1) * 8) * 2;
#pragma unroll
    for (int p = 0; p < 4; p++)
        offB[p] = ((wn + p * 16 + (sub >> 1) * 8 + r) * ROWH + (sub & 1) * 8) * 2;

    const int lrow = tid >> 1, lcol = (tid & 1) * 8;
    const uint32_t sd0 = (uint32_t)(lrow * ROWH + lcol) * 2;
    const uint32_t sd1 = sd0 + 64 * ROWH * 2;
    const size_t aoff = ((size_t)(b * 128 + sB + (lrow >> 3))) * 4096 +
                        (size_t)(lrow & 7) * 512 + lcol;
    const __half* PAh = g_phi + pb + aoff;
    const __half* PAl = g_plo + pb + aoff;
    const __half* PBh = Rh + (size_t)lrow * 512 + lcol;
    const __half* PBl = Rl + (size_t)lrow * 512 + lcol;

    float acc[4][8][4] = {};

#define G2_LOAD(kc, buf)                                                 \
    {                                                                    \
        const uint32_t bb_ = sb + (buf) * BUFB;                          \
        const int ko_ = (kc) * 16;                                       \
        cp16(bb_ + 0 * MATB + sd0, PAh + ko_);                           \
        cp16(bb_ + 0 * MATB + sd1, PAh + ko_ + (size_t)8 * 4096);        \
        cp16(bb_ + 1 * MATB + sd0, PAl + ko_);                           \
        cp16(bb_ + 1 * MATB + sd1, PAl + ko_ + (size_t)8 * 4096);        \
        cp16(bb_ + 2 * MATB + sd0, PBh + ko_);                           \
        cp16(bb_ + 2 * MATB + sd1, PBh + ko_ + (size_t)64 * 512);        \
        cp16(bb_ + 3 * MATB + sd0, PBl + ko_);                           \
        cp16(bb_ + 3 * MATB + sd1, PBl + ko_ + (size_t)64 * 512);        \
    }

    G2_LOAD(0, 0);
    cp_commit();
    G2_LOAD(1, 1);
    cp_commit();
    G2_LOAD(2, 2);
    cp_commit();

#pragma unroll 1
    for (int c = 0; c < 32; c++) {
        cp_wait2();
        __syncthreads();
        const uint32_t mb = sb + (c & 3) * BUFB;
        if (c + 3 < 32) G2_LOAD(c + 3, (c + 3) & 3);
        cp_commit();
        WARP_TILE_BODY64(mb, offA, offB, acc);
    }

    // Epilogue part 1: tanh, weight by v[g] (k = g per lane), shfl-reduce k.
    const float* vv = br ? vp : va;
    const float vg = vv[g];
#pragma unroll
    for (int fm = 0; fm < 4; fm++)
#pragma unroll
        for (int fn = 0; fn < 8; fn++)
#pragma unroll
            for (int j = 0; j < 4; j++)
                acc[fm][fn][j] = vg * tanhf(acc[fm][fn][j]);
#pragma unroll
    for (int off = 16; off >= 4; off >>= 1)
#pragma unroll
        for (int fm = 0; fm < 4; fm++)
#pragma unroll
            for (int fn = 0; fn < 8; fn++)
#pragma unroll
                for (int j = 0; j < 4; j++)
                    acc[fm][fn][j] +=
                        __shfl_xor_sync(0xffffffffu, acc[fm][fn][j], off);

    __syncthreads();  // mainloop smem dead; reuse as score tile [16][132]
    if (lane < 4) {   // g == 0 lanes hold the k-sums
#pragma unroll
        for (int fm = 0; fm < 4; fm++)
#pragma unroll
            for (int si = 0; si < 2; si++) {
                const int srow = (wm >> 3) + 2 * fm + si;
#pragma unroll
                for (int fn = 0; fn < 8; fn++) {
                    sc[srow * 132 + wn + fn * 8 + tig * 2] = acc[fm][fn][si * 2];
                    sc[srow * 132 + wn + fn * 8 + tig * 2 + 1] =
                        acc[fm][fn][si * 2 + 1];
                }
            }
    }
    __syncthreads();

    // Epilogue part 2: softmax over t=128 per s row (8 threads/row).
    {
        const int row = tid >> 3, l8 = tid & 7;
        float vals[16];
        float mx = -1e30f;
#pragma unroll
        for (int i = 0; i < 16; i++) {
            vals[i] = sc[row * 132 + l8 * 16 + i];
            mx = fmaxf(mx, vals[i]);
        }
#pragma unroll
        for (int off = 1; off <= 4; off <<= 1)
            mx = fmaxf(mx, __shfl_xor_sync(0xffffffffu, mx, off));
        float sm = 0.f;
#pragma unroll
        for (int i = 0; i < 16; i++) {
            vals[i] = expf(vals[i] - mx);
            sm += vals[i];
        }
#pragma unroll
        for (int off = 1; off <= 4; off <<= 1)
            sm += __shfl_xor_sync(0xffffffffu, sm, off);
        const float inv = 1.f / sm;
        const size_t base = (size_t)z * 16384 + (size_t)(sB + row) * 128 + l8 * 16;
#pragma unroll
        for (int i = 0; i < 16; i += 2) {
            __half h0, l0, h1, l1;
            split_h(vals[i] * inv, h0, l0);
            split_h(vals[i + 1] * inv, h1, l1);
            *(__half2*)&g_ath[base + i] = __halves2half2(h0, h1);
            *(__half2*)&g_atl[base + i] = __halves2half2(l0, l1);
        }
    }
}

// ===========================================================================
// GEMM3 (fp16 3x split, NT): out = bias + attn[128,128] @ V^T[512,128]^T
// grid (4 h-blocks, 64 z), 256 threads, CTA 128x128, K = t = 128 (8 chunks).
// [R14/R15 proven]
// ===========================================================================
__global__ __launch_bounds__(256) void k_gemm3(const float* __restrict__ aspect,
                                               const float* __restrict__ polarity,
                                               float* __restrict__ out) {
    extern __shared__ __half sh[];
    const uint32_t sb = smem_to_u32(sh);
    const int tid = threadIdx.x;
    const int wid = tid >> 5, lane = tid & 31;
    const int g = lane >> 2, tig = lane & 3;
    const int sub = lane >> 3, r = lane & 7;
    const int wm = (wid & 3) * 32, wn = (wid >> 2) * 64;

    const int z = blockIdx.y;
    const int br = z >> 5, b = z & 31;
    const int h0 = blockIdx.x * 128;

    const int vsel = br ? 0 : 1;
    const __half* Ah = g_ath + (size_t)z * 16384;
    const __half* Al = g_atl + (size_t)z * 16384;
    const __half* Bh = g_vth + ((size_t)(vsel * 32 + b) * 512 + h0) * 128;
    const __half* Bl = g_vtl + ((size_t)(vsel * 32 + b) * 512 + h0) * 128;

    uint32_t offA[2];
#pragma unroll
    for (int fm = 0; fm < 2; fm++)
        offA[fm] = ((wm + fm * 16 + (sub & 1) * 8 + r) * ROWH + (sub >> 1) * 8) * 2;
    uint32_t offB[4];
#pragma unroll
    for (int p = 0; p < 4; p++)
        offB[p] = ((wn + p * 16 + (sub >> 1) * 8 + r) * ROWH + (sub & 1) * 8) * 2;

    const int lrow = tid >> 1, lh = (tid & 1) * 8;
    const uint32_t sdst = (uint32_t)(lrow * ROWH + lh) * 2;

    float acc[2][8][4] = {};

#define G3_LOAD(kc, buf)                                                    \
    {                                                                       \
        const uint32_t bb_ = sb + (buf) * BUFB;                             \
        const size_t so_ = (size_t)lrow * 128 + (kc) * 16 + lh;             \
        cp16(bb_ + 0 * MATB + sdst, Ah + so_);                              \
        cp16(bb_ + 1 * MATB + sdst, Al + so_);                              \
        cp16(bb_ + 2 * MATB + sdst, Bh + so_);                              \
        cp16(bb_ + 3 * MATB + sdst, Bl + so_);                              \
    }

    G3_LOAD(0, 0);
    cp_commit();
    G3_LOAD(1, 1);
    cp_commit();

#pragma unroll 1
    for (int c = 0; c < 8; c++) {
        cp_wait1();
        __syncthreads();
        const int buf = c % 3;
        if (c + 2 < 8) G3_LOAD(c + 2, (c + 2) % 3);
        cp_commit();
        const uint32_t mb = sb + buf * BUFB;

        uint32_t ah[2][4], al[2][4];
#pragma unroll
        for (int fm = 0; fm < 2; fm++) {
            ldsm4(ah[fm][0], ah[fm][1], ah[fm][2], ah[fm][3], mb + 0 * MATB + offA[fm]);
            ldsm4(al[fm][0], al[fm][1], al[fm][2], al[fm][3], mb + 1 * MATB + offA[fm]);
        }
        uint32_t bh[8][2], bl[8][2];
#pragma unroll
        for (int p = 0; p < 4; p++) {
            ldsm4(bh[2 * p][0], bh[2 * p][1], bh[2 * p + 1][0], bh[2 * p + 1][1],
                  mb + 2 * MATB + offB[p]);
            ldsm4(bl[2 * p][0], bl[2 * p][1], bl[2 * p + 1][0], bl[2 * p + 1][1],
                  mb + 3 * MATB + offB[p]);
        }
#pragma unroll
        for (int fm = 0; fm < 2; fm++)
#pragma unroll
            for (int fn = 0; fn < 8; fn++) {
                mma16816(acc[fm][fn], ah[fm], bh[fn]);
                mma16816(acc[fm][fn], ah[fm], bl[fn]);
                mma16816(acc[fm][fn], al[fm], bh[fn]);
            }
    }

    const float* bias = (br ? polarity : aspect) + (size_t)b * 128 * 512;
    float* C = out + (size_t)br * (32 * 128 * 512) + (size_t)b * 128 * 512;
#pragma unroll
    for (int fm = 0; fm < 2; fm++)
#pragma unroll
        for (int fn = 0; fn < 8; fn++) {
            const int row = wm + fm * 16 + g;
            const int col = h0 + wn + fn * 8 + tig * 2;
            size_t o = (size_t)row * 512 + col;
            float2 bv = *(const float2*)&bias[o];
            *(float2*)&C[o] =
                make_float2(bv.x + acc[fm][fn][0], bv.y + acc[fm][fn][1]);
            o += (size_t)8 * 512;
            bv = *(const float2*)&bias[o];
            *(float2*)&C[o] =
                make_float2(bv.x + acc[fm][fn][2], bv.y + acc[fm][fn][3]);
        }
}

// ---------------------------------------------------------------------------
extern "C" void kernel_launch(void* const* d_in, const int* in_sizes, int n_in,
                              void* d_out, int out_size) {
    const float* aspect = (const float*)d_in[0];
    const float* polarity = (const float*)d_in[1];
    const float* Gap = (const float*)d_in[2];
    const float* Gpa = (const float*)d_in[3];
    const float* va = (const float*)d_in[4];
    const float* vp = (const float*)d_in[5];
    float* out = (float*)d_out;

    cudaFuncSetAttribute(k_gemm1, cudaFuncAttributeMaxDynamicSharedMemorySize, GSMEM1);
    cudaFuncSetAttribute(k_gemm2, cudaFuncAttributeMaxDynamicSharedMemorySize, GSMEM1);
    cudaFuncSetAttribute(k_gemm3, cudaFuncAttributeMaxDynamicSharedMemorySize, GSMEM);

    k_prep_xv<<<dim3(16, 4, 64), dim3(32, 8)>>>(aspect, polarity);
    k_prep_g<<<dim3(128, 16, 2), dim3(32, 8)>>>(Gap, Gpa);
    k_gemm1<<<dim3(32, 32, 2), 128, GSMEM1>>>();
    k_gemm2<<<dim3(8, 64), 128, GSMEM1>>>(va, vp);
    k_gemm3<<<dim3(4, 64), 256, GSMEM>>>(aspect, polarity, out);
}